// round 12
// baseline (speedup 1.0000x reference)
#include <cuda_runtime.h>
#include <cuda_bf16.h>
#include <cuda_fp16.h>
#include <mma.h>
#include <cstdint>

using namespace nvcuda;

#define B_  512
#define T_  256
#define V_  1000
#define E_  256
#define H_  512
#define G_  2048   // 4*H

#define LDW 520    // padded bf16 smem pitch (1040B) — conflict-free
#define LDG_ 132   // padded float pitch for gate buffer

// ---------------- fast activations / helpers ----------------
__device__ __forceinline__ float tanh_fast(float x) {
    float y; asm("tanh.approx.f32 %0, %1;" : "=f"(y) : "f"(x)); return y;
}
__device__ __forceinline__ float sigmoid_fast(float x) {
    return fmaf(0.5f, tanh_fast(0.5f * x), 0.5f);
}
__device__ __forceinline__ void st_release_gpu(int* p, int v) {
    asm volatile("st.release.gpu.global.b32 [%0], %1;" :: "l"(p), "r"(v) : "memory");
}
__device__ __forceinline__ int ld_acquire_gpu(const int* p) {
    int v;
    asm volatile("ld.acquire.gpu.global.b32 %0, [%1];" : "=r"(v) : "l"(p) : "memory");
    return v;
}
__device__ __forceinline__ uint32_t smem_u32(const void* p) {
    uint32_t a;
    asm("{ .reg .u64 t; cvta.to.shared.u64 t, %1; cvt.u32.u64 %0, t; }" : "=r"(a) : "l"(p));
    return a;
}
#define CP_ASYNC16(sa, gp) \
    asm volatile("cp.async.cg.shared.global [%0], [%1], 16;" :: "r"(sa), "l"(gp) : "memory")
#define CP_COMMIT()  asm volatile("cp.async.commit_group;" ::: "memory")
#define CP_WAIT1()   asm volatile("cp.async.wait_group 1;" ::: "memory")
#define CP_WAIT0()   asm volatile("cp.async.wait_group 0;" ::: "memory")
#define LDMATRIX_X4(r0, r1, r2, r3, addr) \
    asm volatile("ldmatrix.sync.aligned.m8n8.x4.shared.b16 {%0,%1,%2,%3}, [%4];" \
        : "=r"(r0), "=r"(r1), "=r"(r2), "=r"(r3) : "r"(addr))
#define MMA_16816(d, a0, a1, a2, a3, b0, b1) \
    asm volatile("mma.sync.aligned.m16n8k16.row.col.f32.bf16.bf16.f32 " \
        "{%0,%1,%2,%3}, {%4,%5,%6,%7}, {%8,%9}, {%0,%1,%2,%3};" \
        : "+f"(d[0]), "+f"(d[1]), "+f"(d[2]), "+f"(d[3]) \
        : "r"(a0), "r"(a1), "r"(a2), "r"(a3), "r"(b0), "r"(b1))

// ---------------- static device scratch ----------------
__device__ __align__(16) __nv_bfloat16 g_H[(T_ + 1)][B_][H_];   // h states (~134MB)
__device__ __align__(16) float          g_tab[V_][G_];          // interleaved [v][4*h+q] (8MB)
__device__ __align__(16) __nv_bfloat16  g_Whh[G_][H_];          // bf16 W_hh1 (2MB)
__device__ __align__(16) __nv_bfloat16  g_Wout[1024][H_];       // bf16 W_out padded (1MB)
__device__ __align__(16) __half         g_logits[T_ * B_][1024];// fp16 logits scratch (268MB)
__device__ __align__(16) short          g_chars[T_][B_];
__device__ int g_flags[128 * 32];        // per-(bt,gt) monotone step flags, 128B apart

// ---------------- init ----------------
__global__ void init_kernel(const float* __restrict__ Whh1, const float* __restrict__ WoutF,
                            const void* __restrict__ gt_raw) {
    int stride = gridDim.x * blockDim.x;
    int tid0 = blockIdx.x * blockDim.x + threadIdx.x;
    if (tid0 < 128) g_flags[tid0 * 32] = 0;
    const int* p = (const int*)gt_raw;
    int z = (p[1] == 0) + (p[3] == 0) + (p[5] == 0) + (p[7] == 0) +
            (p[9] == 0) + (p[11] == 0) + (p[13] == 0) + (p[15] == 0);
    int is64 = (z == 8);
    for (int i = tid0; i < G_ * H_; i += stride) {
        ((__nv_bfloat16*)g_Whh)[i] = __float2bfloat16(Whh1[i]);
        if (i < 1024 * H_) {
            float v = (i < V_ * H_) ? WoutF[i] : 0.f;
            ((__nv_bfloat16*)g_Wout)[i] = __float2bfloat16(v);
        }
        if (i < B_ * H_) ((__nv_bfloat16*)g_H)[i] = __float2bfloat16(0.f);
        if (i < T_ * B_) {
            int t = i / B_, b = i % B_;
            int ch = 0;
            if (t > 0) {
                int idx = b * T_ + (t - 1);
                ch = is64 ? (int)((const long long*)gt_raw)[idx] : ((const int*)gt_raw)[idx];
            }
            ((short*)g_chars)[i] = (short)ch;
        }
    }
}

// ---------------- ih gate table (interleaved [v][4*h+q]) ----------------
__global__ void table_kernel(const float* __restrict__ emb, const float* __restrict__ Wih,
                             const float* __restrict__ bih, const float* __restrict__ bhh) {
    int gtile = blockIdx.x;
    int vtile = blockIdx.y;
    __shared__ float sE[64][65];
    __shared__ float sW[64][65];
    float acc[4][4] = {};
    int tm = threadIdx.x >> 4, tn = threadIdx.x & 15;
    for (int kc = 0; kc < 4; kc++) {
        for (int i = threadIdx.x; i < 64 * 64; i += 256) {
            int r = i >> 6, c = i & 63;
            int v = vtile * 64 + r;
            sE[r][c] = (v < V_) ? emb[v * E_ + kc * 64 + c] : 0.f;
            sW[r][c] = Wih[(gtile * 64 + r) * E_ + kc * 64 + c];
        }
        __syncthreads();
        #pragma unroll 8
        for (int k = 0; k < 64; k++) {
            float e[4], w[4];
            #pragma unroll
            for (int mi = 0; mi < 4; mi++) e[mi] = sE[tm * 4 + mi][k];
            #pragma unroll
            for (int ni = 0; ni < 4; ni++) w[ni] = sW[tn * 4 + ni][k];
            #pragma unroll
            for (int mi = 0; mi < 4; mi++)
                #pragma unroll
                for (int ni = 0; ni < 4; ni++) acc[mi][ni] += e[mi] * w[ni];
        }
        __syncthreads();
    }
    #pragma unroll
    for (int mi = 0; mi < 4; mi++) {
        int v = vtile * 64 + tm * 4 + mi;
        if (v >= V_) continue;
        #pragma unroll
        for (int ni = 0; ni < 4; ni++) {
            int g = gtile * 64 + tn * 4 + ni;            // gate-major index q*512+h
            g_tab[v][(g & 511) * 4 + (g >> 9)] = acc[mi][ni] + bih[g] + bhh[g];
        }
    }
}

// ---------------- persistent recurrence: split-barrier pipelined staging ----------------
// 128 blocks: bt = bid>>4 (8 x 64 batch), gt = bid&15 (16 x 32 h-cols -> 128 gate cols).
// Step top: warp w polls peer w (K cols 0..255 half) and stages its slice; then peer 8+w.
// GEMM1 starts after only the first half; second half's lag + staging hides under GEMM1.
#define SMEM_RECUR ((128 * LDW + 64 * LDW) * 2)

__global__ __launch_bounds__(256, 1) void recur_kernel() {
    extern __shared__ __nv_bfloat16 smem[];
    __nv_bfloat16* sW = smem;               // 128 x LDW
    __nv_bfloat16* sA = smem + 128 * LDW;   // 64 x LDW
    float* sG = (float*)sA;                 // 64 x LDG_ (reuse after GEMM)

    const int gt = blockIdx.x & 15;
    const int bt = blockIdx.x >> 4;
    const int b0 = bt * 64;
    const int tid = threadIdx.x;

    // stage W slice once: row r: gate q=r>>5, h-col gt*32+(r&31)
    for (int i = tid; i < 128 * 64; i += 256) {
        int r = i >> 6, c = i & 63;
        int grow = (r >> 5) * H_ + gt * 32 + (r & 31);
        ((uint4*)(sW + r * LDW))[c] = *(const uint4*)&g_Whh[grow][c * 8];
    }
    __syncthreads();

    const int warp = tid >> 5, lane = tid & 31;
    const int wm = warp >> 2;
    const int wn = warp & 3;
    const int hcol = gt * 32 + lane;
    const uint32_t sAaddr = smem_u32(sA);

    int* myflag = &g_flags[(bt * 16 + gt) * 32];
    const int* peerA = &g_flags[(bt * 16 + warp) * 32];       // peers 0..7  -> K cols 0..255
    const int* peerB = &g_flags[(bt * 16 + 8 + warp) * 32];   // peers 8..15 -> K cols 256..511

    float creg[8];
    #pragma unroll
    for (int j = 0; j < 8; j++) creg[j] = 0.f;

    for (int t = 0; t < T_; t++) {
        short chs[8];
        #pragma unroll
        for (int k = 0; k < 8; k++) chs[k] = g_chars[t][b0 + warp + 8 * k];

        // ---- phase A: wait peer `warp`, stage its 64x64B slice (K cols warp*32..+31) ----
        if (lane == 0) { while (ld_acquire_gpu(peerA) < t) __nanosleep(32); }
        __syncwarp();
        #pragma unroll
        for (int i = 0; i < 8; i++) {
            int idx = i * 32 + lane;             // 0..255
            int r = idx >> 2, c = idx & 3;       // row, 16B chunk
            CP_ASYNC16(sAaddr + (uint32_t)(r * (LDW * 2) + warp * 64 + c * 16),
                       (const char*)&g_H[t][b0 + r][warp * 32 + c * 8]);
        }
        CP_COMMIT();

        // ---- phase B: wait peer 8+warp, stage its slice (K cols 256+warp*32..) ----
        if (lane == 0) { while (ld_acquire_gpu(peerB) < t) __nanosleep(32); }
        __syncwarp();
        #pragma unroll
        for (int i = 0; i < 8; i++) {
            int idx = i * 32 + lane;
            int r = idx >> 2, c = idx & 3;
            CP_ASYNC16(sAaddr + (uint32_t)(r * (LDW * 2) + 512 + warp * 64 + c * 16),
                       (const char*)&g_H[t][b0 + r][256 + warp * 32 + c * 8]);
        }
        CP_COMMIT();

        wmma::fragment<wmma::accumulator, 16, 16, 16, float> acc[2][2];
        #pragma unroll
        for (int mi = 0; mi < 2; mi++)
            #pragma unroll
            for (int ni = 0; ni < 2; ni++) wmma::fill_fragment(acc[mi][ni], 0.f);

        CP_WAIT1();          // first K-half landed
        __syncthreads();

        #pragma unroll 4
        for (int kk = 0; kk < 16; kk++) {
            wmma::fragment<wmma::matrix_b, 16, 16, 16, __nv_bfloat16, wmma::col_major> fb[2];
            #pragma unroll
            for (int ni = 0; ni < 2; ni++)
                wmma::load_matrix_sync(fb[ni], sW + (wn * 32 + ni * 16) * LDW + kk * 16, LDW);
            #pragma unroll
            for (int mi = 0; mi < 2; mi++) {
                wmma::fragment<wmma::matrix_a, 16, 16, 16, __nv_bfloat16, wmma::row_major> fa;
                wmma::load_matrix_sync(fa, sA + (wm * 32 + mi * 16) * LDW + kk * 16, LDW);
                #pragma unroll
                for (int ni = 0; ni < 2; ni++)
                    wmma::mma_sync(acc[mi][ni], fa, fb[ni], acc[mi][ni]);
            }
        }

        CP_WAIT0();          // second K-half landed (hidden under first-half GEMM)
        __syncthreads();

        #pragma unroll 4
        for (int kk = 16; kk < 32; kk++) {
            wmma::fragment<wmma::matrix_b, 16, 16, 16, __nv_bfloat16, wmma::col_major> fb[2];
            #pragma unroll
            for (int ni = 0; ni < 2; ni++)
                wmma::load_matrix_sync(fb[ni], sW + (wn * 32 + ni * 16) * LDW + kk * 16, LDW);
            #pragma unroll
            for (int mi = 0; mi < 2; mi++) {
                wmma::fragment<wmma::matrix_a, 16, 16, 16, __nv_bfloat16, wmma::row_major> fa;
                wmma::load_matrix_sync(fa, sA + (wm * 32 + mi * 16) * LDW + kk * 16, LDW);
                #pragma unroll
                for (int ni = 0; ni < 2; ni++)
                    wmma::mma_sync(acc[mi][ni], fa, fb[ni], acc[mi][ni]);
            }
        }
        __syncthreads();

        #pragma unroll
        for (int mi = 0; mi < 2; mi++)
            #pragma unroll
            for (int ni = 0; ni < 2; ni++)
                wmma::store_matrix_sync(sG + (wm * 32 + mi * 16) * LDG_ + (wn * 32 + ni * 16),
                                        acc[mi][ni], LDG_, wmma::mem_row_major);
        __syncthreads();

        #pragma unroll
        for (int k = 0; k < 8; k++) {
            int bl = warp + 8 * k;
            float4 tb = ((const float4*)g_tab[(int)chs[k]])[hcol];
            float gi = sG[bl * LDG_ + lane]      + tb.x;
            float gf = sG[bl * LDG_ + 32 + lane] + tb.y;
            float gg = sG[bl * LDG_ + 64 + lane] + tb.z;
            float go = sG[bl * LDG_ + 96 + lane] + tb.w;
            gi = sigmoid_fast(gi);
            gf = sigmoid_fast(gf);
            gg = tanh_fast(gg);
            go = sigmoid_fast(go);
            float c = fmaf(gf, creg[k], gi * gg);
            creg[k] = c;
            g_H[t + 1][b0 + bl][hcol] = __float2bfloat16(go * tanh_fast(c));
        }

        // release: all h_{t+1} stores for this block are visible before flag = t+1
        __syncthreads();
        if (tid == 0) st_release_gpu(myflag, t + 1);
    }
}

// ---------------- projection: raw mma, block 128m x 256n (512 thr), direct fp16 stores ----------------
#define LOGITS_SMEM ((128 * 72 + 256 * 72) * 2)

__global__ __launch_bounds__(512, 1) void logits_kernel() {
    extern __shared__ __nv_bfloat16 lsm[];
    __nv_bfloat16* sA = lsm;             // 128 x 72
    __nv_bfloat16* sB = lsm + 128 * 72;  // 256 x 72
    const __nv_bfloat16* A = &g_H[1][0][0];  // [131072][512]

    const int nt = blockIdx.x, mt = blockIdx.y;
    const int tid = threadIdx.x, warp = tid >> 5, lane = tid & 31;
    const int wm = warp >> 2, wn = warp & 3;     // wm 0..3 (32 rows), wn 0..3 (64 cols)
    const int g8 = lane >> 2, t4 = lane & 3;

    const uint32_t sA32 = smem_u32(sA), sB32 = smem_u32(sB);
    uint32_t aAddr[2], bAddr[4];
    #pragma unroll
    for (int mi = 0; mi < 2; mi++)
        aAddr[mi] = sA32 + (uint32_t)(((wm * 32 + mi * 16 + (lane & 15)) * 72 + (lane >> 4) * 8) * 2);
    #pragma unroll
    for (int nj = 0; nj < 4; nj++)
        bAddr[nj] = sB32 + (uint32_t)(((wn * 64 + nj * 16 + (lane & 15)) * 72 + (lane >> 4) * 8) * 2);

    float acc[2][8][4];
    #pragma unroll
    for (int mi = 0; mi < 2; mi++)
        #pragma unroll
        for (int n8 = 0; n8 < 8; n8++)
            #pragma unroll
            for (int e = 0; e < 4; e++) acc[mi][n8][e] = 0.f;

    for (int kc = 0; kc < 8; kc++) {
        #pragma unroll
        for (int i = tid; i < 1024; i += 512) {              // A chunk 128x64
            int r = i >> 3, c8 = i & 7;
            *(uint4*)(sA + r * 72 + c8 * 8) =
                *(const uint4*)&A[(mt * 128 + r) * 512 + kc * 64 + c8 * 8];
        }
        #pragma unroll
        for (int i = tid; i < 2048; i += 512) {              // B chunk 256x64
            int n = i >> 3, c8 = i & 7;
            *(uint4*)(sB + n * 72 + c8 * 8) =
                *(const uint4*)&g_Wout[nt * 256 + n][kc * 64 + c8 * 8];
        }
        __syncthreads();
        #pragma unroll
        for (int kk = 0; kk < 4; kk++) {
            uint32_t a[2][4];
            #pragma unroll
            for (int mi = 0; mi < 2; mi++)
                LDMATRIX_X4(a[mi][0], a[mi][1], a[mi][2], a[mi][3], aAddr[mi] + kk * 32);
            #pragma unroll
            for (int nj = 0; nj < 4; nj++) {
                uint32_t bm[4];
                LDMATRIX_X4(bm[0], bm[1], bm[2], bm[3], bAddr[nj] + kk * 32);
                #pragma unroll
                for (int mi = 0; mi < 2; mi++) {
                    MMA_16816(acc[mi][nj * 2 + 0], a[mi][0], a[mi][1], a[mi][2], a[mi][3],
                              bm[0], bm[2]);
                    MMA_16816(acc[mi][nj * 2 + 1], a[mi][0], a[mi][1], a[mi][2], a[mi][3],
                              bm[1], bm[3]);
                }
            }
        }
        __syncthreads();
    }

    // direct fp16 stores from accumulators (layout verified)
    #pragma unroll
    for (int mi = 0; mi < 2; mi++) {
        int row = mt * 128 + wm * 32 + mi * 16 + g8;
        #pragma unroll
        for (int n8 = 0; n8 < 8; n8++) {
            int col = nt * 256 + wn * 64 + n8 * 8 + 2 * t4;
            *(__half2*)&g_logits[row][col] = __floats2half2_rn(acc[mi][n8][0], acc[mi][n8][1]);
            *(__half2*)&g_logits[row + 8][col] = __floats2half2_rn(acc[mi][n8][2], acc[mi][n8][3]);
        }
    }
}

// ---------------- log_softmax + bias + remap (fp16 input) ----------------
__global__ __launch_bounds__(256, 4) void softmax_kernel(float* __restrict__ out,
                                                         const float* __restrict__ bout) {
    int row = blockIdx.x;
    int t = row >> 9, b = row & 511;
    const __half* lg = g_logits[row];
    __shared__ float red[8];

    int lane = threadIdx.x & 31;
    int warp = threadIdx.x >> 5;

    float v[4];
    float mx = -1e30f;
    #pragma unroll
    for (int j = 0; j < 4; j++) {
        int c = threadIdx.x + j * 256;
        v[j] = (c < V_) ? (__half2float(lg[c]) + bout[c]) : -1e30f;
        mx = fmaxf(mx, v[j]);
    }
    #pragma unroll
    for (int s = 16; s > 0; s >>= 1) mx = fmaxf(mx, __shfl_xor_sync(0xFFFFFFFF, mx, s));
    if (lane == 0) red[warp] = mx;
    __syncthreads();
    float m0 = red[lane & 7];
    #pragma unroll
    for (int s = 4; s > 0; s >>= 1) m0 = fmaxf(m0, __shfl_xor_sync(0xFFFFFFFF, m0, s));
    mx = m0;

    float sum = 0.f;
    #pragma unroll
    for (int j = 0; j < 4; j++) {
        int c = threadIdx.x + j * 256;
        if (c < V_) sum += __expf(v[j] - mx);
    }
    #pragma unroll
    for (int s = 16; s > 0; s >>= 1) sum += __shfl_xor_sync(0xFFFFFFFF, sum, s);
    __syncthreads();
    if (lane == 0) red[warp] = sum;
    __syncthreads();
    float s0 = red[lane & 7];
    #pragma unroll
    for (int s = 4; s > 0; s >>= 1) s0 += __shfl_xor_sync(0xFFFFFFFF, s0, s);
    float lse = mx + logf(s0);

    float* o = out + ((size_t)b * T_ + t) * V_;
    #pragma unroll
    for (int j = 0; j < 4; j++) {
        int c = threadIdx.x + j * 256;
        if (c < V_) o[c] = v[j] - lse;
    }
}

// ---------------- launch ----------------
extern "C" void kernel_launch(void* const* d_in, const int* in_sizes, int n_in,
                              void* d_out, int out_size) {
    const void*  gt   = d_in[1];
    const float* emb  = (const float*)d_in[2];
    const float* Wih1 = (const float*)d_in[7];
    const float* Whh1 = (const float*)d_in[8];
    const float* bih1 = (const float*)d_in[9];
    const float* bhh1 = (const float*)d_in[10];
    const float* Wout = (const float*)d_in[11];
    const float* bout = (const float*)d_in[12];
    float* out = (float*)d_out;

    cudaFuncSetAttribute(recur_kernel, cudaFuncAttributeMaxDynamicSharedMemorySize, SMEM_RECUR);
    cudaFuncSetAttribute(logits_kernel, cudaFuncAttributeMaxDynamicSharedMemorySize, LOGITS_SMEM);

    init_kernel<<<1024, 256>>>(Whh1, Wout, gt);
    table_kernel<<<dim3(32, 16), 256>>>(emb, Wih1, bih1, bhh1);
    recur_kernel<<<128, 256, SMEM_RECUR>>>();
    logits_kernel<<<dim3(4, 1024), 512, LOGITS_SMEM>>>();
    softmax_kernel<<<T_ * B_, 256>>>(out, bout);
}

// round 13
// speedup vs baseline: 1.0465x; 1.0465x over previous
#include <cuda_runtime.h>
#include <cuda_bf16.h>
#include <cuda_fp16.h>
#include <mma.h>
#include <cstdint>

using namespace nvcuda;

#define B_  512
#define T_  256
#define V_  1000
#define E_  256
#define H_  512
#define G_  2048   // 4*H

#define LDW 520    // padded bf16 smem pitch (1040B) — conflict-free
#define LDG_ 132   // padded float pitch for gate buffer

// ---------------- fast activations / helpers ----------------
__device__ __forceinline__ float tanh_fast(float x) {
    float y; asm("tanh.approx.f32 %0, %1;" : "=f"(y) : "f"(x)); return y;
}
__device__ __forceinline__ float sigmoid_fast(float x) {
    return fmaf(0.5f, tanh_fast(0.5f * x), 0.5f);
}
__device__ __forceinline__ void st_release_gpu(int* p, int v) {
    asm volatile("st.release.gpu.global.b32 [%0], %1;" :: "l"(p), "r"(v) : "memory");
}
__device__ __forceinline__ int ld_acquire_gpu(const int* p) {
    int v;
    asm volatile("ld.acquire.gpu.global.b32 %0, [%1];" : "=r"(v) : "l"(p) : "memory");
    return v;
}
__device__ __forceinline__ uint32_t smem_u32(const void* p) {
    uint32_t a;
    asm("{ .reg .u64 t; cvta.to.shared.u64 t, %1; cvt.u32.u64 %0, t; }" : "=r"(a) : "l"(p));
    return a;
}
#define CP_ASYNC16(sa, gp) \
    asm volatile("cp.async.cg.shared.global [%0], [%1], 16;" :: "r"(sa), "l"(gp) : "memory")
#define CP_COMMIT()  asm volatile("cp.async.commit_group;" ::: "memory")
#define CP_WAIT1()   asm volatile("cp.async.wait_group 1;" ::: "memory")
#define CP_WAIT0()   asm volatile("cp.async.wait_group 0;" ::: "memory")
#define LDMATRIX_X4(r0, r1, r2, r3, addr) \
    asm volatile("ldmatrix.sync.aligned.m8n8.x4.shared.b16 {%0,%1,%2,%3}, [%4];" \
        : "=r"(r0), "=r"(r1), "=r"(r2), "=r"(r3) : "r"(addr))
#define MMA_16816(d, a0, a1, a2, a3, b0, b1) \
    asm volatile("mma.sync.aligned.m16n8k16.row.col.f32.bf16.bf16.f32 " \
        "{%0,%1,%2,%3}, {%4,%5,%6,%7}, {%8,%9}, {%0,%1,%2,%3};" \
        : "+f"(d[0]), "+f"(d[1]), "+f"(d[2]), "+f"(d[3]) \
        : "r"(a0), "r"(a1), "r"(a2), "r"(a3), "r"(b0), "r"(b1))

// ---------------- static device scratch ----------------
__device__ __align__(16) __nv_bfloat16 g_H[(T_ + 1)][B_][H_];   // h states (~134MB)
__device__ __align__(16) float          g_tab[V_][G_];          // interleaved [v][4*h+q] (8MB)
__device__ __align__(16) __nv_bfloat16  g_Whh[G_][H_];          // bf16 W_hh1 (2MB)
__device__ __align__(16) __nv_bfloat16  g_Wout[1024][H_];       // bf16 W_out padded (1MB)
__device__ __align__(16) __half         g_logits[T_ * B_][1024];// fp16 logits scratch (268MB)
__device__ __align__(16) short          g_chars[T_][B_];
__device__ int g_flags[128 * 32];        // per-(bt,gt) monotone step flags, 128B apart

// ---------------- init ----------------
__global__ void init_kernel(const float* __restrict__ Whh1, const float* __restrict__ WoutF,
                            const void* __restrict__ gt_raw) {
    int stride = gridDim.x * blockDim.x;
    int tid0 = blockIdx.x * blockDim.x + threadIdx.x;
    if (tid0 < 128) g_flags[tid0 * 32] = 0;
    const int* p = (const int*)gt_raw;
    int z = (p[1] == 0) + (p[3] == 0) + (p[5] == 0) + (p[7] == 0) +
            (p[9] == 0) + (p[11] == 0) + (p[13] == 0) + (p[15] == 0);
    int is64 = (z == 8);
    for (int i = tid0; i < G_ * H_; i += stride) {
        ((__nv_bfloat16*)g_Whh)[i] = __float2bfloat16(Whh1[i]);
        if (i < 1024 * H_) {
            float v = (i < V_ * H_) ? WoutF[i] : 0.f;
            ((__nv_bfloat16*)g_Wout)[i] = __float2bfloat16(v);
        }
        if (i < B_ * H_) ((__nv_bfloat16*)g_H)[i] = __float2bfloat16(0.f);
        if (i < T_ * B_) {
            int t = i / B_, b = i % B_;
            int ch = 0;
            if (t > 0) {
                int idx = b * T_ + (t - 1);
                ch = is64 ? (int)((const long long*)gt_raw)[idx] : ((const int*)gt_raw)[idx];
            }
            ((short*)g_chars)[i] = (short)ch;
        }
    }
}

// ---------------- ih gate table (interleaved [v][4*h+q]) ----------------
__global__ void table_kernel(const float* __restrict__ emb, const float* __restrict__ Wih,
                             const float* __restrict__ bih, const float* __restrict__ bhh) {
    int gtile = blockIdx.x;
    int vtile = blockIdx.y;
    __shared__ float sE[64][65];
    __shared__ float sW[64][65];
    float acc[4][4] = {};
    int tm = threadIdx.x >> 4, tn = threadIdx.x & 15;
    for (int kc = 0; kc < 4; kc++) {
        for (int i = threadIdx.x; i < 64 * 64; i += 256) {
            int r = i >> 6, c = i & 63;
            int v = vtile * 64 + r;
            sE[r][c] = (v < V_) ? emb[v * E_ + kc * 64 + c] : 0.f;
            sW[r][c] = Wih[(gtile * 64 + r) * E_ + kc * 64 + c];
        }
        __syncthreads();
        #pragma unroll 8
        for (int k = 0; k < 64; k++) {
            float e[4], w[4];
            #pragma unroll
            for (int mi = 0; mi < 4; mi++) e[mi] = sE[tm * 4 + mi][k];
            #pragma unroll
            for (int ni = 0; ni < 4; ni++) w[ni] = sW[tn * 4 + ni][k];
            #pragma unroll
            for (int mi = 0; mi < 4; mi++)
                #pragma unroll
                for (int ni = 0; ni < 4; ni++) acc[mi][ni] += e[mi] * w[ni];
        }
        __syncthreads();
    }
    #pragma unroll
    for (int mi = 0; mi < 4; mi++) {
        int v = vtile * 64 + tm * 4 + mi;
        if (v >= V_) continue;
        #pragma unroll
        for (int ni = 0; ni < 4; ni++) {
            int g = gtile * 64 + tn * 4 + ni;            // gate-major index q*512+h
            g_tab[v][(g & 511) * 4 + (g >> 9)] = acc[mi][ni] + bih[g] + bhh[g];
        }
    }
}

// ---------------- persistent recurrence (round-10 trunk, unchanged) ----------------
#define SMEM_RECUR ((128 * LDW + 64 * LDW) * 2)

__global__ __launch_bounds__(256, 1) void recur_kernel() {
    extern __shared__ __nv_bfloat16 smem[];
    __nv_bfloat16* sW = smem;               // 128 x LDW
    __nv_bfloat16* sA = smem + 128 * LDW;   // 64 x LDW
    float* sG = (float*)sA;                 // 64 x LDG_ (reuse after GEMM)

    const int gt = blockIdx.x & 15;
    const int bt = blockIdx.x >> 4;
    const int b0 = bt * 64;
    const int tid = threadIdx.x;

    for (int i = tid; i < 128 * 64; i += 256) {
        int r = i >> 6, c = i & 63;
        int grow = (r >> 5) * H_ + gt * 32 + (r & 31);
        ((uint4*)(sW + r * LDW))[c] = *(const uint4*)&g_Whh[grow][c * 8];
    }
    __syncthreads();

    const int warp = tid >> 5, lane = tid & 31;
    const int wm = warp >> 2;
    const int wn = warp & 3;
    const int hcol = gt * 32 + lane;
    const uint32_t sAaddr = smem_u32(sA);

    int* myflag = &g_flags[(bt * 16 + gt) * 32];
    int* peerflag = &g_flags[(bt * 16 + (tid & 15)) * 32];

    float creg[8];
    #pragma unroll
    for (int j = 0; j < 8; j++) creg[j] = 0.f;

    for (int t = 0; t < T_; t++) {
        short chs[8];
        #pragma unroll
        for (int k = 0; k < 8; k++) chs[k] = g_chars[t][b0 + warp + 8 * k];

        #pragma unroll
        for (int i = tid; i < 2048; i += 256) {              // cols 0..255
            int r = i >> 5, c = i & 31;
            CP_ASYNC16(sAaddr + (uint32_t)((r * LDW + c * 8) * 2),
                       (const char*)&g_H[t][b0 + r][c * 8]);
        }
        CP_COMMIT();
        #pragma unroll
        for (int i = tid; i < 2048; i += 256) {              // cols 256..511
            int r = i >> 5, c = (i & 31) + 32;
            CP_ASYNC16(sAaddr + (uint32_t)((r * LDW + c * 8) * 2),
                       (const char*)&g_H[t][b0 + r][c * 8]);
        }
        CP_COMMIT();

        wmma::fragment<wmma::accumulator, 16, 16, 16, float> acc[2][2];
        #pragma unroll
        for (int mi = 0; mi < 2; mi++)
            #pragma unroll
            for (int ni = 0; ni < 2; ni++) wmma::fill_fragment(acc[mi][ni], 0.f);

        CP_WAIT1();
        __syncthreads();

        #pragma unroll 4
        for (int kk = 0; kk < 16; kk++) {
            wmma::fragment<wmma::matrix_b, 16, 16, 16, __nv_bfloat16, wmma::col_major> fb[2];
            #pragma unroll
            for (int ni = 0; ni < 2; ni++)
                wmma::load_matrix_sync(fb[ni], sW + (wn * 32 + ni * 16) * LDW + kk * 16, LDW);
            #pragma unroll
            for (int mi = 0; mi < 2; mi++) {
                wmma::fragment<wmma::matrix_a, 16, 16, 16, __nv_bfloat16, wmma::row_major> fa;
                wmma::load_matrix_sync(fa, sA + (wm * 32 + mi * 16) * LDW + kk * 16, LDW);
                #pragma unroll
                for (int ni = 0; ni < 2; ni++)
                    wmma::mma_sync(acc[mi][ni], fa, fb[ni], acc[mi][ni]);
            }
        }

        CP_WAIT0();
        __syncthreads();

        #pragma unroll 4
        for (int kk = 16; kk < 32; kk++) {
            wmma::fragment<wmma::matrix_b, 16, 16, 16, __nv_bfloat16, wmma::col_major> fb[2];
            #pragma unroll
            for (int ni = 0; ni < 2; ni++)
                wmma::load_matrix_sync(fb[ni], sW + (wn * 32 + ni * 16) * LDW + kk * 16, LDW);
            #pragma unroll
            for (int mi = 0; mi < 2; mi++) {
                wmma::fragment<wmma::matrix_a, 16, 16, 16, __nv_bfloat16, wmma::row_major> fa;
                wmma::load_matrix_sync(fa, sA + (wm * 32 + mi * 16) * LDW + kk * 16, LDW);
                #pragma unroll
                for (int ni = 0; ni < 2; ni++)
                    wmma::mma_sync(acc[mi][ni], fa, fb[ni], acc[mi][ni]);
            }
        }
        __syncthreads();

        #pragma unroll
        for (int mi = 0; mi < 2; mi++)
            #pragma unroll
            for (int ni = 0; ni < 2; ni++)
                wmma::store_matrix_sync(sG + (wm * 32 + mi * 16) * LDG_ + (wn * 32 + ni * 16),
                                        acc[mi][ni], LDG_, wmma::mem_row_major);
        __syncthreads();

        #pragma unroll
        for (int k = 0; k < 8; k++) {
            int bl = warp + 8 * k;
            float4 tb = ((const float4*)g_tab[(int)chs[k]])[hcol];
            float gi = sG[bl * LDG_ + lane]      + tb.x;
            float gf = sG[bl * LDG_ + 32 + lane] + tb.y;
            float gg = sG[bl * LDG_ + 64 + lane] + tb.z;
            float go = sG[bl * LDG_ + 96 + lane] + tb.w;
            gi = sigmoid_fast(gi);
            gf = sigmoid_fast(gf);
            gg = tanh_fast(gg);
            go = sigmoid_fast(go);
            float c = fmaf(gf, creg[k], gi * gg);
            creg[k] = c;
            g_H[t + 1][b0 + bl][hcol] = __float2bfloat16(go * tanh_fast(c));
        }

        __syncthreads();
        if (tid == 0) st_release_gpu(myflag, t + 1);
        if (tid < 16) {
            while (ld_acquire_gpu(peerflag) < t + 1) __nanosleep(32);
        }
        __syncthreads();
    }
}

// ---------------- projection: raw mma, 64m x 256n, cp.async double-buffered ----------------
// Per stage: sA 64x72 + sB 256x72 bf16 = 46080B; 2 stages = 92160B; 2 blocks/SM = 180KB.
#define STG_BYTES (46080)
#define LOGITS_SMEM (2 * STG_BYTES)

__global__ __launch_bounds__(256, 2) void logits_kernel() {
    extern __shared__ __nv_bfloat16 lsm[];
    const __nv_bfloat16* A = &g_H[1][0][0];  // [131072][512]

    const int nt = blockIdx.x, mt = blockIdx.y;
    const int tid = threadIdx.x, warp = tid >> 5, lane = tid & 31;
    const int wm = warp >> 2, wn = warp & 3;
    const int g8 = lane >> 2, t4 = lane & 3;

    const uint32_t base = smem_u32(lsm);
    const uint32_t sBoff = 64 * 72 * 2;      // B region offset within a stage

    // ldmatrix base addresses (stage 0); add stage offset at use
    uint32_t aAddr[2], bAddr[4];
    #pragma unroll
    for (int mi = 0; mi < 2; mi++)
        aAddr[mi] = base + (uint32_t)(((wm * 32 + mi * 16 + (lane & 15)) * 72 + (lane >> 4) * 8) * 2);
    #pragma unroll
    for (int nj = 0; nj < 4; nj++)
        bAddr[nj] = base + sBoff + (uint32_t)(((wn * 64 + nj * 16 + (lane & 15)) * 72 + (lane >> 4) * 8) * 2);

    float acc[2][8][4];
    #pragma unroll
    for (int mi = 0; mi < 2; mi++)
        #pragma unroll
        for (int n8 = 0; n8 < 8; n8++)
            #pragma unroll
            for (int e = 0; e < 4; e++) acc[mi][n8][e] = 0.f;

    // staging: A chunk 64x64 (512 x 16B), B chunk 256x64 (2048 x 16B)
    auto stage = [&](int kc, uint32_t soff) {
        #pragma unroll
        for (int i = tid; i < 512; i += 256) {
            int r = i >> 3, c8 = i & 7;
            CP_ASYNC16(base + soff + (uint32_t)((r * 72 + c8 * 8) * 2),
                       (const char*)&A[(mt * 64 + r) * 512 + kc * 64 + c8 * 8]);
        }
        #pragma unroll
        for (int i = tid; i < 2048; i += 256) {
            int n = i >> 3, c8 = i & 7;
            CP_ASYNC16(base + soff + sBoff + (uint32_t)((n * 72 + c8 * 8) * 2),
                       (const char*)&g_Wout[nt * 256 + n][kc * 64 + c8 * 8]);
        }
        CP_COMMIT();
    };

    stage(0, 0);

    for (int kc = 0; kc < 8; kc++) {
        uint32_t cur = (uint32_t)(kc & 1) * STG_BYTES;
        CP_WAIT0();          // only the current chunk's group is in flight
        __syncthreads();     // all threads past previous math; buffer handoff safe
        if (kc < 7) stage(kc + 1, (uint32_t)((kc + 1) & 1) * STG_BYTES);

        #pragma unroll
        for (int kk = 0; kk < 4; kk++) {
            uint32_t a[2][4];
            #pragma unroll
            for (int mi = 0; mi < 2; mi++)
                LDMATRIX_X4(a[mi][0], a[mi][1], a[mi][2], a[mi][3], aAddr[mi] + cur + kk * 32);
            #pragma unroll
            for (int nj = 0; nj < 4; nj++) {
                uint32_t bm[4];
                LDMATRIX_X4(bm[0], bm[1], bm[2], bm[3], bAddr[nj] + cur + kk * 32);
                #pragma unroll
                for (int mi = 0; mi < 2; mi++) {
                    MMA_16816(acc[mi][nj * 2 + 0], a[mi][0], a[mi][1], a[mi][2], a[mi][3],
                              bm[0], bm[2]);
                    MMA_16816(acc[mi][nj * 2 + 1], a[mi][0], a[mi][1], a[mi][2], a[mi][3],
                              bm[1], bm[3]);
                }
            }
        }
    }

    // direct fp16 stores from accumulators (layout verified)
    #pragma unroll
    for (int mi = 0; mi < 2; mi++) {
        int row = mt * 64 + wm * 32 + mi * 16 + g8;
        #pragma unroll
        for (int n8 = 0; n8 < 8; n8++) {
            int col = nt * 256 + wn * 64 + n8 * 8 + 2 * t4;
            *(__half2*)&g_logits[row][col] = __floats2half2_rn(acc[mi][n8][0], acc[mi][n8][1]);
            *(__half2*)&g_logits[row + 8][col] = __floats2half2_rn(acc[mi][n8][2], acc[mi][n8][3]);
        }
    }
}

// ---------------- log_softmax + bias + remap (fp16 input) ----------------
__global__ __launch_bounds__(256, 4) void softmax_kernel(float* __restrict__ out,
                                                         const float* __restrict__ bout) {
    int row = blockIdx.x;
    int t = row >> 9, b = row & 511;
    const __half* lg = g_logits[row];
    __shared__ float red[8];

    int lane = threadIdx.x & 31;
    int warp = threadIdx.x >> 5;

    float v[4];
    float mx = -1e30f;
    #pragma unroll
    for (int j = 0; j < 4; j++) {
        int c = threadIdx.x + j * 256;
        v[j] = (c < V_) ? (__half2float(lg[c]) + bout[c]) : -1e30f;
        mx = fmaxf(mx, v[j]);
    }
    #pragma unroll
    for (int s = 16; s > 0; s >>= 1) mx = fmaxf(mx, __shfl_xor_sync(0xFFFFFFFF, mx, s));
    if (lane == 0) red[warp] = mx;
    __syncthreads();
    float m0 = red[lane & 7];
    #pragma unroll
    for (int s = 4; s > 0; s >>= 1) m0 = fmaxf(m0, __shfl_xor_sync(0xFFFFFFFF, m0, s));
    mx = m0;

    float sum = 0.f;
    #pragma unroll
    for (int j = 0; j < 4; j++) {
        int c = threadIdx.x + j * 256;
        if (c < V_) sum += __expf(v[j] - mx);
    }
    #pragma unroll
    for (int s = 16; s > 0; s >>= 1) sum += __shfl_xor_sync(0xFFFFFFFF, sum, s);
    __syncthreads();
    if (lane == 0) red[warp] = sum;
    __syncthreads();
    float s0 = red[lane & 7];
    #pragma unroll
    for (int s = 4; s > 0; s >>= 1) s0 += __shfl_xor_sync(0xFFFFFFFF, s0, s);
    float lse = mx + logf(s0);

    float* o = out + ((size_t)b * T_ + t) * V_;
    #pragma unroll
    for (int j = 0; j < 4; j++) {
        int c = threadIdx.x + j * 256;
        if (c < V_) o[c] = v[j] - lse;
    }
}

// ---------------- launch ----------------
extern "C" void kernel_launch(void* const* d_in, const int* in_sizes, int n_in,
                              void* d_out, int out_size) {
    const void*  gt   = d_in[1];
    const float* emb  = (const float*)d_in[2];
    const float* Wih1 = (const float*)d_in[7];
    const float* Whh1 = (const float*)d_in[8];
    const float* bih1 = (const float*)d_in[9];
    const float* bhh1 = (const float*)d_in[10];
    const float* Wout = (const float*)d_in[11];
    const float* bout = (const float*)d_in[12];
    float* out = (float*)d_out;

    cudaFuncSetAttribute(recur_kernel, cudaFuncAttributeMaxDynamicSharedMemorySize, SMEM_RECUR);
    cudaFuncSetAttribute(logits_kernel, cudaFuncAttributeMaxDynamicSharedMemorySize, LOGITS_SMEM);

    init_kernel<<<1024, 256>>>(Whh1, Wout, gt);
    table_kernel<<<dim3(32, 16), 256>>>(emb, Wih1, bih1, bhh1);
    recur_kernel<<<128, 256, SMEM_RECUR>>>();
    logits_kernel<<<dim3(4, 2048), 256, LOGITS_SMEM>>>();
    softmax_kernel<<<T_ * B_, 256>>>(out, bout);
}

// round 16
// speedup vs baseline: 1.1247x; 1.0747x over previous
#include <cuda_runtime.h>
#include <cuda_bf16.h>
#include <cuda_fp16.h>
#include <mma.h>
#include <cstdint>

using namespace nvcuda;

#define B_  512
#define T_  256
#define V_  1000
#define E_  256
#define H_  512
#define G_  2048   // 4*H

#define LDW 520    // padded bf16 smem pitch (1040B) — conflict-free
#define LDG_ 132

// ---------------- fast activations / helpers ----------------
__device__ __forceinline__ float tanh_fast(float x) {
    float y; asm("tanh.approx.f32 %0, %1;" : "=f"(y) : "f"(x)); return y;
}
__device__ __forceinline__ float sigmoid_fast(float x) {
    return fmaf(0.5f, tanh_fast(0.5f * x), 0.5f);
}
__device__ __forceinline__ void st_release_gpu(int* p, int v) {
    asm volatile("st.release.gpu.global.b32 [%0], %1;" :: "l"(p), "r"(v) : "memory");
}
__device__ __forceinline__ int ld_acquire_gpu(const int* p) {
    int v;
    asm volatile("ld.acquire.gpu.global.b32 %0, [%1];" : "=r"(v) : "l"(p) : "memory");
    return v;
}
__device__ __forceinline__ uint32_t smem_u32(const void* p) {
    uint32_t a;
    asm("{ .reg .u64 t; cvta.to.shared.u64 t, %1; cvt.u32.u64 %0, t; }" : "=r"(a) : "l"(p));
    return a;
}
#define CP_ASYNC16(sa, gp) \
    asm volatile("cp.async.cg.shared.global [%0], [%1], 16;" :: "r"(sa), "l"(gp) : "memory")
#define CP_COMMIT()  asm volatile("cp.async.commit_group;" ::: "memory")
#define CP_WAIT1()   asm volatile("cp.async.wait_group 1;" ::: "memory")
#define CP_WAIT0()   asm volatile("cp.async.wait_group 0;" ::: "memory")
#define LDMATRIX_X4(r0, r1, r2, r3, addr) \
    asm volatile("ldmatrix.sync.aligned.m8n8.x4.shared.b16 {%0,%1,%2,%3}, [%4];" \
        : "=r"(r0), "=r"(r1), "=r"(r2), "=r"(r3) : "r"(addr))
#define MMA_16816(d, a0, a1, a2, a3, b0, b1) \
    asm volatile("mma.sync.aligned.m16n8k16.row.col.f32.bf16.bf16.f32 " \
        "{%0,%1,%2,%3}, {%4,%5,%6,%7}, {%8,%9}, {%0,%1,%2,%3};" \
        : "+f"(d[0]), "+f"(d[1]), "+f"(d[2]), "+f"(d[3]) \
        : "r"(a0), "r"(a1), "r"(a2), "r"(a3), "r"(b0), "r"(b1))

// ---------------- static device scratch ----------------
__device__ __align__(16) __nv_bfloat16 g_H[(T_ + 1)][B_][H_];   // h states (~134MB)
__device__ __align__(16) float          g_tab[V_][G_];          // interleaved [v][4*h+q] (8MB)
__device__ __align__(16) __nv_bfloat16  g_Whh[G_][H_];          // bf16 W_hh1 (2MB)
__device__ __align__(16) __nv_bfloat16  g_Wout[1024][H_];       // bf16 W_out padded (1MB)
__device__ __align__(16) __half         g_logits[T_ * B_][1024];// fp16 logits scratch (268MB)
__device__ __align__(16) short          g_chars[T_][B_];
__device__ int g_flags[128 * 32];        // per-(bt,gt) monotone step flags, 128B apart

// ---------------- init ----------------
__global__ void init_kernel(const float* __restrict__ Whh1, const float* __restrict__ WoutF,
                            const void* __restrict__ gt_raw) {
    int stride = gridDim.x * blockDim.x;
    int tid0 = blockIdx.x * blockDim.x + threadIdx.x;
    if (tid0 < 128) g_flags[tid0 * 32] = 0;
    const int* p = (const int*)gt_raw;
    int z = (p[1] == 0) + (p[3] == 0) + (p[5] == 0) + (p[7] == 0) +
            (p[9] == 0) + (p[11] == 0) + (p[13] == 0) + (p[15] == 0);
    int is64 = (z == 8);
    for (int i = tid0; i < G_ * H_; i += stride) {
        ((__nv_bfloat16*)g_Whh)[i] = __float2bfloat16(Whh1[i]);
        if (i < 1024 * H_) {
            float v = (i < V_ * H_) ? WoutF[i] : 0.f;
            ((__nv_bfloat16*)g_Wout)[i] = __float2bfloat16(v);
        }
        if (i < B_ * H_) ((__nv_bfloat16*)g_H)[i] = __float2bfloat16(0.f);
        if (i < T_ * B_) {
            int t = i / B_, b = i % B_;
            int ch = 0;
            if (t > 0) {
                int idx = b * T_ + (t - 1);
                ch = is64 ? (int)((const long long*)gt_raw)[idx] : ((const int*)gt_raw)[idx];
            }
            ((short*)g_chars)[i] = (short)ch;
        }
    }
}

// ---------------- ih gate table (interleaved [v][4*h+q]) ----------------
__global__ void table_kernel(const float* __restrict__ emb, const float* __restrict__ Wih,
                             const float* __restrict__ bih, const float* __restrict__ bhh) {
    int gtile = blockIdx.x;
    int vtile = blockIdx.y;
    __shared__ float sE[64][65];
    __shared__ float sW[64][65];
    float acc[4][4] = {};
    int tm = threadIdx.x >> 4, tn = threadIdx.x & 15;
    for (int kc = 0; kc < 4; kc++) {
        for (int i = threadIdx.x; i < 64 * 64; i += 256) {
            int r = i >> 6, c = i & 63;
            int v = vtile * 64 + r;
            sE[r][c] = (v < V_) ? emb[v * E_ + kc * 64 + c] : 0.f;
            sW[r][c] = Wih[(gtile * 64 + r) * E_ + kc * 64 + c];
        }
        __syncthreads();
        #pragma unroll 8
        for (int k = 0; k < 64; k++) {
            float e[4], w[4];
            #pragma unroll
            for (int mi = 0; mi < 4; mi++) e[mi] = sE[tm * 4 + mi][k];
            #pragma unroll
            for (int ni = 0; ni < 4; ni++) w[ni] = sW[tn * 4 + ni][k];
            #pragma unroll
            for (int mi = 0; mi < 4; mi++)
                #pragma unroll
                for (int ni = 0; ni < 4; ni++) acc[mi][ni] += e[mi] * w[ni];
        }
        __syncthreads();
    }
    #pragma unroll
    for (int mi = 0; mi < 4; mi++) {
        int v = vtile * 64 + tm * 4 + mi;
        if (v >= V_) continue;
        #pragma unroll
        for (int ni = 0; ni < 4; ni++) {
            int g = gtile * 64 + tn * 4 + ni;            // gate-major index q*512+h
            g_tab[v][(g & 511) * 4 + (g >> 9)] = acc[mi][ni] + bih[g] + bhh[g];
        }
    }
}

// ---------------- persistent recurrence: raw mma, register-resident gates ----------------
// 128 blocks: bt = bid>>4 (8 x 64 batch), gt = bid&15 (16 x 32 h-cols).
// W' rows n = 4*h_local + q (verified mapping, round 6). Gates merge via shfl.xor(1);
// no gate SMEM round-trip, 3 syncthreads/step.
#define SMEM_RECUR ((128 * LDW + 64 * LDW) * 2)

__global__ __launch_bounds__(256, 1) void recur_kernel() {
    extern __shared__ __nv_bfloat16 smem[];
    __nv_bfloat16* sW = smem;               // 128 x LDW (W' interleaved rows)
    __nv_bfloat16* sA = smem + 128 * LDW;   // 64 x LDW

    const int gt = blockIdx.x & 15;
    const int bt = blockIdx.x >> 4;
    const int b0 = bt * 64;
    const int tid = threadIdx.x;

    // stage W' once: row n -> g_Whh[(n&3)*512 + gt*32 + (n>>2)]
    for (int i = tid; i < 128 * 64; i += 256) {
        int n = i >> 6, c = i & 63;
        int grow = (n & 3) * H_ + gt * 32 + (n >> 2);
        ((uint4*)(sW + n * LDW))[c] = *(const uint4*)&g_Whh[grow][c * 8];
    }
    __syncthreads();

    const int warp = tid >> 5, lane = tid & 31;
    const int wm = warp >> 2;       // 0..1 : 32 batch rows
    const int wn = warp & 3;        // 0..3 : 32 n-cols (8 h x 4 gates)
    const int g8 = lane >> 2;
    const int t4 = lane & 3;
    const int odd = t4 & 1;
    const int tb2 = t4 >> 1;
    const uint32_t sAaddr = smem_u32(sA);
    const uint32_t sA32 = sAaddr, sW32 = smem_u32(sW);

    uint32_t aAddr[2], bAddr[2];
    #pragma unroll
    for (int mi = 0; mi < 2; mi++)
        aAddr[mi] = sA32 + (uint32_t)(((wm * 32 + mi * 16 + (lane & 15)) * LDW + (lane >> 4) * 8) * 2);
    #pragma unroll
    for (int nj = 0; nj < 2; nj++)
        bAddr[nj] = sW32 + (uint32_t)(((wn * 32 + nj * 16 + (lane & 15)) * LDW + (lane >> 4) * 8) * 2);

    int bb[2];
    #pragma unroll
    for (int mi = 0; mi < 2; mi++) bb[mi] = b0 + wm * 32 + mi * 16 + g8 + odd * 8;
    int hc[4];
    #pragma unroll
    for (int ni = 0; ni < 4; ni++) hc[ni] = gt * 32 + wn * 8 + 2 * ni + tb2;

    int* myflag = &g_flags[(bt * 16 + gt) * 32];
    int* peerflag = &g_flags[(bt * 16 + (tid & 15)) * 32];

    float creg[2][4];
    #pragma unroll
    for (int mi = 0; mi < 2; mi++)
        #pragma unroll
        for (int ni = 0; ni < 4; ni++) creg[mi][ni] = 0.f;

    for (int t = 0; t < T_; t++) {
        // prefetch 2 chars (depend only on t)
        short chs[2];
        #pragma unroll
        for (int mi = 0; mi < 2; mi++) chs[mi] = g_chars[t][bb[mi]];

        // stage A = h_t [64 x 512] via cp.async, two K-halves
        #pragma unroll
        for (int i = tid; i < 2048; i += 256) {              // cols 0..255
            int r = i >> 5, c = i & 31;
            CP_ASYNC16(sAaddr + (uint32_t)((r * LDW + c * 8) * 2),
                       (const char*)&g_H[t][b0 + r][c * 8]);
        }
        CP_COMMIT();
        #pragma unroll
        for (int i = tid; i < 2048; i += 256) {              // cols 256..511
            int r = i >> 5, c = (i & 31) + 32;
            CP_ASYNC16(sAaddr + (uint32_t)((r * LDW + c * 8) * 2),
                       (const char*)&g_H[t][b0 + r][c * 8]);
        }
        CP_COMMIT();

        float acc[2][4][4];
        #pragma unroll
        for (int mi = 0; mi < 2; mi++)
            #pragma unroll
            for (int ni = 0; ni < 4; ni++)
                #pragma unroll
                for (int e = 0; e < 4; e++) acc[mi][ni][e] = 0.f;

        CP_WAIT1();
        __syncthreads();

        #pragma unroll 4
        for (int kk = 0; kk < 16; kk++) {
            uint32_t a[2][4], bm[2][4];
            #pragma unroll
            for (int mi = 0; mi < 2; mi++)
                LDMATRIX_X4(a[mi][0], a[mi][1], a[mi][2], a[mi][3], aAddr[mi] + kk * 32);
            #pragma unroll
            for (int nj = 0; nj < 2; nj++)
                LDMATRIX_X4(bm[nj][0], bm[nj][1], bm[nj][2], bm[nj][3], bAddr[nj] + kk * 32);
            #pragma unroll
            for (int mi = 0; mi < 2; mi++)
                #pragma unroll
                for (int nj = 0; nj < 2; nj++) {
                    MMA_16816(acc[mi][nj * 2 + 0], a[mi][0], a[mi][1], a[mi][2], a[mi][3],
                              bm[nj][0], bm[nj][2]);
                    MMA_16816(acc[mi][nj * 2 + 1], a[mi][0], a[mi][1], a[mi][2], a[mi][3],
                              bm[nj][1], bm[nj][3]);
                }
        }

        CP_WAIT0();
        __syncthreads();

        #pragma unroll 4
        for (int kk = 16; kk < 32; kk++) {
            uint32_t a[2][4], bm[2][4];
            #pragma unroll
            for (int mi = 0; mi < 2; mi++)
                LDMATRIX_X4(a[mi][0], a[mi][1], a[mi][2], a[mi][3], aAddr[mi] + kk * 32);
            #pragma unroll
            for (int nj = 0; nj < 2; nj++)
                LDMATRIX_X4(bm[nj][0], bm[nj][1], bm[nj][2], bm[nj][3], bAddr[nj] + kk * 32);
            #pragma unroll
            for (int mi = 0; mi < 2; mi++)
                #pragma unroll
                for (int nj = 0; nj < 2; nj++) {
                    MMA_16816(acc[mi][nj * 2 + 0], a[mi][0], a[mi][1], a[mi][2], a[mi][3],
                              bm[nj][0], bm[nj][2]);
                    MMA_16816(acc[mi][nj * 2 + 1], a[mi][0], a[mi][1], a[mi][2], a[mi][3],
                              bm[nj][1], bm[nj][3]);
                }
        }

        // register-resident epilogue (mapping verified round 6): shfl merges (i,f)/(g,o)
        #pragma unroll
        for (int mi = 0; mi < 2; mi++) {
            const float4* trow = (const float4*)g_tab[(int)chs[mi]];
            #pragma unroll
            for (int ni = 0; ni < 4; ni++) {
                float c0 = acc[mi][ni][0], c1 = acc[mi][ni][1];
                float c2 = acc[mi][ni][2], c3 = acc[mi][ni][3];
                float u = odd ? c0 : c2;
                float v = odd ? c1 : c3;
                float ru = __shfl_xor_sync(0xFFFFFFFF, u, 1);
                float rv = __shfl_xor_sync(0xFFFFFFFF, v, 1);
                float gi = odd ? ru : c0;
                float gf = odd ? rv : c1;
                float gg = odd ? c2 : ru;
                float go = odd ? c3 : rv;
                float4 tb = trow[hc[ni]];
                gi = sigmoid_fast(gi + tb.x);
                gf = sigmoid_fast(gf + tb.y);
                gg = tanh_fast(gg + tb.z);
                go = sigmoid_fast(go + tb.w);
                float cv = fmaf(gf, creg[mi][ni], gi * gg);
                creg[mi][ni] = cv;
                g_H[t + 1][bb[mi]][hc[ni]] = __float2bfloat16(go * tanh_fast(cv));
            }
        }

        // release/acquire barrier across the 16 gt blocks of this bt
        __syncthreads();                 // all warps done with sA + h stores issued
        if (tid == 0) st_release_gpu(myflag, t + 1);
        if (tid < 16) {
            while (ld_acquire_gpu(peerflag) < t + 1) __nanosleep(32);
        }
        __syncthreads();
    }
}

// ---------------- projection: raw mma, 64m x 256n, cp.async double-buffered ----------------
#define STG_BYTES (46080)
#define LOGITS_SMEM (2 * STG_BYTES)

__global__ __launch_bounds__(256, 2) void logits_kernel() {
    extern __shared__ __nv_bfloat16 lsm[];
    const __nv_bfloat16* A = &g_H[1][0][0];  // [131072][512]

    const int nt = blockIdx.x, mt = blockIdx.y;
    const int tid = threadIdx.x, warp = tid >> 5, lane = tid & 31;
    const int wm = warp >> 2, wn = warp & 3;
    const int g8 = lane >> 2, t4 = lane & 3;

    const uint32_t base = smem_u32(lsm);
    const uint32_t sBoff = 64 * 72 * 2;

    uint32_t aAddr[2], bAddr[4];
    #pragma unroll
    for (int mi = 0; mi < 2; mi++)
        aAddr[mi] = base + (uint32_t)(((wm * 32 + mi * 16 + (lane & 15)) * 72 + (lane >> 4) * 8) * 2);
    #pragma unroll
    for (int nj = 0; nj < 4; nj++)
        bAddr[nj] = base + sBoff + (uint32_t)(((wn * 64 + nj * 16 + (lane & 15)) * 72 + (lane >> 4) * 8) * 2);

    float acc[2][8][4];
    #pragma unroll
    for (int mi = 0; mi < 2; mi++)
        #pragma unroll
        for (int n8 = 0; n8 < 8; n8++)
            #pragma unroll
            for (int e = 0; e < 4; e++) acc[mi][n8][e] = 0.f;

    auto stage = [&](int kc, uint32_t soff) {
        #pragma unroll
        for (int i = tid; i < 512; i += 256) {
            int r = i >> 3, c8 = i & 7;
            CP_ASYNC16(base + soff + (uint32_t)((r * 72 + c8 * 8) * 2),
                       (const char*)&A[(mt * 64 + r) * 512 + kc * 64 + c8 * 8]);
        }
        #pragma unroll
        for (int i = tid; i < 2048; i += 256) {
            int n = i >> 3, c8 = i & 7;
            CP_ASYNC16(base + soff + sBoff + (uint32_t)((n * 72 + c8 * 8) * 2),
                       (const char*)&g_Wout[nt * 256 + n][kc * 64 + c8 * 8]);
        }
        CP_COMMIT();
    };

    stage(0, 0);

    for (int kc = 0; kc < 8; kc++) {
        uint32_t cur = (uint32_t)(kc & 1) * STG_BYTES;
        CP_WAIT0();
        __syncthreads();
        if (kc < 7) stage(kc + 1, (uint32_t)((kc + 1) & 1) * STG_BYTES);

        #pragma unroll
        for (int kk = 0; kk < 4; kk++) {
            uint32_t a[2][4];
            #pragma unroll
            for (int mi = 0; mi < 2; mi++)
                LDMATRIX_X4(a[mi][0], a[mi][1], a[mi][2], a[mi][3], aAddr[mi] + cur + kk * 32);
            #pragma unroll
            for (int nj = 0; nj < 4; nj++) {
                uint32_t bm[4];
                LDMATRIX_X4(bm[0], bm[1], bm[2], bm[3], bAddr[nj] + cur + kk * 32);
                #pragma unroll
                for (int mi = 0; mi < 2; mi++) {
                    MMA_16816(acc[mi][nj * 2 + 0], a[mi][0], a[mi][1], a[mi][2], a[mi][3],
                              bm[0], bm[2]);
                    MMA_16816(acc[mi][nj * 2 + 1], a[mi][0], a[mi][1], a[mi][2], a[mi][3],
                              bm[1], bm[3]);
                }
            }
        }
    }

    #pragma unroll
    for (int mi = 0; mi < 2; mi++) {
        int row = mt * 64 + wm * 32 + mi * 16 + g8;
        #pragma unroll
        for (int n8 = 0; n8 < 8; n8++) {
            int col = nt * 256 + wn * 64 + n8 * 8 + 2 * t4;
            *(__half2*)&g_logits[row][col] = __floats2half2_rn(acc[mi][n8][0], acc[mi][n8][1]);
            *(__half2*)&g_logits[row + 8][col] = __floats2half2_rn(acc[mi][n8][2], acc[mi][n8][3]);
        }
    }
}

// ---------------- log_softmax + bias + remap (vectorized half2/float2) ----------------
__global__ __launch_bounds__(256, 4) void softmax_kernel(float* __restrict__ out,
                                                         const float* __restrict__ bout) {
    int row = blockIdx.x;
    int t = row >> 9, b = row & 511;
    const __half* lg = g_logits[row];
    __shared__ float red[8];

    int lane = threadIdx.x & 31;
    int warp = threadIdx.x >> 5;

    float v[4];
    float mx = -1e30f;
    #pragma unroll
    for (int j = 0; j < 2; j++) {
        int c2 = 2 * (threadIdx.x + j * 256);            // even; V_=1000 even
        if (c2 < V_) {
            __half2 h2 = *(const __half2*)&lg[c2];
            float2 b2 = *(const float2*)&bout[c2];
            v[2 * j]     = __half2float(__low2half(h2))  + b2.x;
            v[2 * j + 1] = __half2float(__high2half(h2)) + b2.y;
        } else {
            v[2 * j] = -1e30f; v[2 * j + 1] = -1e30f;
        }
        mx = fmaxf(mx, fmaxf(v[2 * j], v[2 * j + 1]));
    }
    #pragma unroll
    for (int s = 16; s > 0; s >>= 1) mx = fmaxf(mx, __shfl_xor_sync(0xFFFFFFFF, mx, s));
    if (lane == 0) red[warp] = mx;
    __syncthreads();
    float m0 = red[lane & 7];
    #pragma unroll
    for (int s = 4; s > 0; s >>= 1) m0 = fmaxf(m0, __shfl_xor_sync(0xFFFFFFFF, m0, s));
    mx = m0;

    float sum = 0.f;
    #pragma unroll
    for (int j = 0; j < 4; j++) sum += __expf(v[j] - mx);   // padded lanes add exp(-huge)=0
    #pragma unroll
    for (int s = 16; s > 0; s >>= 1) sum += __shfl_xor_sync(0xFFFFFFFF, sum, s);
    __syncthreads();
    if (lane == 0) red[warp] = sum;
    __syncthreads();
    float s0 = red[lane & 7];
    #pragma unroll
    for (int s = 4; s > 0; s >>= 1) s0 += __shfl_xor_sync(0xFFFFFFFF, s0, s);
    float lse = mx + logf(s0);

    float* o = out + ((size_t)b * T_ + t) * V_;
    #pragma unroll
    for (int j = 0; j < 2; j++) {
        int c2 = 2 * (threadIdx.x + j * 256);
        if (c2 < V_) {
            float2 w2 = make_float2(v[2 * j] - lse, v[2 * j + 1] - lse);
            *(float2*)&o[c2] = w2;
        }
    }
}

// ---------------- launch ----------------
extern "C" void kernel_launch(void* const* d_in, const int* in_sizes, int n_in,
                              void* d_out, int out_size) {
    const void*  gt   = d_in[1];
    const float* emb  = (const float*)d_in[2];
    const float* Wih1 = (const float*)d_in[7];
    const float* Whh1 = (const float*)d_in[8];
    const float* bih1 = (const float*)d_in[9];
    const float* bhh1 = (const float*)d_in[10];
    const float* Wout = (const float*)d_in[11];
    const float* bout = (const float*)d_in[12];
    float* out = (float*)d_out;

    cudaFuncSetAttribute(recur_kernel, cudaFuncAttributeMaxDynamicSharedMemorySize, SMEM_RECUR);
    cudaFuncSetAttribute(logits_kernel, cudaFuncAttributeMaxDynamicSharedMemorySize, LOGITS_SMEM);

    init_kernel<<<1024, 256>>>(Whh1, Wout, gt);
    table_kernel<<<dim3(32, 16), 256>>>(emb, Wih1, bih1, bhh1);
    recur_kernel<<<128, 256, SMEM_RECUR>>>();
    logits_kernel<<<dim3(4, 2048), 256, LOGITS_SMEM>>>();
    softmax_kernel<<<T_ * B_, 256>>>(out, bout);
}